// round 3
// baseline (speedup 1.0000x reference)
#include <cuda_runtime.h>

// GCN_33560874451187 — scalarized 2-layer GCN with two-level edge binning.
// N=500000 nodes, E=16000000 edges (int32).
//
// Buckets: b = (col>>14)*32 + (row>>14), 31x31 used of 1024.
// Record:  rowlocal(14) << 14 | collocal(14), 28 bits in a u32.
// deg/agg kernels: 8 blocks per col-bucket; smem accumulator over the 16K-node
// col range; val gathered from a staged 64KB smem slice per row-sub-bucket.

#define NN       500000
#define NE       16000000
#define CBB      14
#define CBS      16384            // nodes per bucket range
#define NCB      31               // ceil(NN/CBS)
#define NBUCKET  1024             // 32*32 id space
#define STRIDE   20480            // per-bucket capacity (mean 17.2K, +25 sigma)
#define BIN_TILE 8192
#define BIN_THR  512
#define AGG_THR  512
#define GRP      8                // block-groups per col-bucket (4 rbs each)

__device__ unsigned g_bins[(size_t)NBUCKET * STRIDE];  // ~80MB
__device__ unsigned g_tail[NBUCKET];
__device__ int      g_deg[NN];
__device__ float    g_dinv[NN];
__device__ float    g_val[NN];
__device__ float    g_acc[NN];

// ---------------------------------------------------------------------------

__global__ void k_init(int n) {
    int i = blockIdx.x * blockDim.x + threadIdx.x;
    if (i < NBUCKET) g_tail[i] = 0u;
    if (i < n) g_deg[i] = 0;
}

// Staged multisplit binning: per-tile smem rank + bulk tail reservation.
// dyn smem: rec[8192] u32 | br[8192] u32 | cnt[1024] | base[1024] = 72KB
__global__ void k_bin(const int* __restrict__ row, const int* __restrict__ col, int e) {
    extern __shared__ unsigned sm[];
    unsigned* s_rec  = sm;                 // 8192
    unsigned* s_br   = sm + BIN_TILE;      // 8192
    unsigned* s_cnt  = sm + 2 * BIN_TILE;  // 1024
    unsigned* s_base = s_cnt + NBUCKET;    // 1024

    int t = threadIdx.x;
    int tb = blockIdx.x * BIN_TILE;
    int nE = e - tb; if (nE > BIN_TILE) nE = BIN_TILE;

    for (int i = t; i < NBUCKET; i += BIN_THR) s_cnt[i] = 0u;
    __syncthreads();

    for (int k = t; k < nE; k += BIN_THR) {
        int r = row[tb + k];
        int c = col[tb + k];
        unsigned b = ((unsigned)(c >> CBB) << 5) | (unsigned)(r >> CBB);
        unsigned rank = atomicAdd(&s_cnt[b], 1u);
        s_rec[k] = ((unsigned)(r & (CBS - 1)) << CBB) | (unsigned)(c & (CBS - 1));
        s_br[k]  = (b << 13) | rank;       // b:10 bits, rank<=8191:13 bits
    }
    __syncthreads();

    for (int b = t; b < NBUCKET; b += BIN_THR) {
        unsigned c = s_cnt[b];
        s_base[b] = c ? atomicAdd(&g_tail[b], c) : 0u;
    }
    __syncthreads();

    for (int k = t; k < nE; k += BIN_THR) {
        unsigned br = s_br[k];
        unsigned b = br >> 13, rank = br & 8191u;
        g_bins[(size_t)b * STRIDE + s_base[b] + rank] = s_rec[k];
    }
}

// In-degree: block = (cb, group of 4 rbs); smem counters over 16K col range.
// dyn smem: 16384 u32 = 64KB
__global__ void k_degb(int n) {
    extern __shared__ unsigned s_cnt[];
    int t = threadIdx.x;
    int cb = blockIdx.x >> 3, g = blockIdx.x & 7;

    for (int i = t; i < CBS; i += AGG_THR) s_cnt[i] = 0u;
    __syncthreads();

    #pragma unroll
    for (int j = 0; j < 4; j++) {
        unsigned b = ((unsigned)cb << 5) | (unsigned)(g * 4 + j);
        unsigned cnt = g_tail[b];
        const unsigned* recs = g_bins + (size_t)b * STRIDE;
        for (unsigned k = t; k < cnt; k += AGG_THR)
            atomicAdd(&s_cnt[recs[k] & (CBS - 1)], 1u);
    }
    __syncthreads();

    int base = cb << CBB;
    for (int i = t; i < CBS; i += AGG_THR) {
        unsigned c = s_cnt[i];
        if (c && base + i < n) atomicAdd(&g_deg[base + i], (int)c);
    }
}

// Aggregation: smem accumulator over col range + staged smem val slice per rb.
// dyn smem: acc[16384] f32 | val[16384] f32 = 128KB
__global__ void k_aggb(int n) {
    extern __shared__ float smf[];
    float* s_acc = smf;          // 16384
    float* s_val = smf + CBS;    // 16384
    int t = threadIdx.x;
    int cb = blockIdx.x >> 3, g = blockIdx.x & 7;

    for (int i = t; i < CBS; i += AGG_THR) s_acc[i] = 0.0f;

    #pragma unroll
    for (int j = 0; j < 4; j++) {
        int rb = g * 4 + j;
        unsigned b = ((unsigned)cb << 5) | (unsigned)rb;
        unsigned cnt = g_tail[b];
        const unsigned* recs = g_bins + (size_t)b * STRIDE;

        // stage this rb's 16K val slice (coalesced)
        int rbase = rb << CBB;
        int rlim = n - rbase; if (rlim > CBS) rlim = CBS;
        __syncthreads();                 // protect s_val reuse across j
        for (int i = t; i < rlim; i += AGG_THR) s_val[i] = g_val[rbase + i];
        __syncthreads();

        for (unsigned k = t; k < cnt; k += AGG_THR) {
            unsigned rec = recs[k];
            atomicAdd(&s_acc[rec & (CBS - 1)], s_val[rec >> CBB]);
        }
    }
    __syncthreads();

    int base = cb << CBB;
    for (int i = t; i < CBS; i += AGG_THR) {
        float v = s_acc[i];
        if (v != 0.0f && base + i < n) atomicAdd(&g_acc[base + i], v);
    }
}

// ---------------------------------------------------------------------------
// node-wise kernels (unchanged math)

__global__ void k_phase1(const float* __restrict__ x, int n) {
    int i = blockIdx.x * blockDim.x + threadIdx.x;
    if (i < n) {
        float dinv = rsqrtf((float)(g_deg[i] + 1));
        g_dinv[i] = dinv;
        float y = dinv * x[i];
        g_val[i] = y;
        g_acc[i] = y;
    }
}

__global__ void k_phase2(const float* __restrict__ W1,
                         const float* __restrict__ b1,
                         const float* __restrict__ W2, int n) {
    int i = blockIdx.x * blockDim.x + threadIdx.x;
    if (i < n) {
        float dinv = g_dinv[i];
        float s1 = dinv * g_acc[i];
        float tacc = 0.0f;
        #pragma unroll
        for (int k = 0; k < 10; k++) {
            float h = fmaf(s1, __ldg(&W1[k]), __ldg(&b1[k]));
            tacc = fmaf(fmaxf(h, 0.0f), __ldg(&W2[k]), tacc);
        }
        float z = dinv * tacc;
        g_val[i] = z;
        g_acc[i] = z;
    }
}

__global__ void k_out(float* __restrict__ out, const float* __restrict__ b2, int n) {
    int i = blockIdx.x * blockDim.x + threadIdx.x;
    if (i < n) {
        float v = fmaf(g_dinv[i], g_acc[i], __ldg(&b2[0]));
        out[i] = fminf(fmaxf(v, -0.5f), 9.5f);
    }
}

// ---------------------------------------------------------------------------

extern "C" void kernel_launch(void* const* d_in, const int* in_sizes, int n_in,
                              void* d_out, int out_size) {
    const float* x   = (const float*)d_in[0];
    const int*   ei  = (const int*)d_in[1];
    const float* W1  = (const float*)d_in[2];
    const float* b1  = (const float*)d_in[3];
    const float* W2  = (const float*)d_in[4];
    const float* b2  = (const float*)d_in[5];
    float*       out = (float*)d_out;

    int n = in_sizes[0];
    int e = in_sizes[1] / 2;
    if (n > NN) n = NN;
    if (e > NE) e = NE;

    const int* row = ei;
    const int* col = ei + e;

    // opt-in dynamic smem (idempotent host calls; not stream ops)
    static bool attr_done = false;
    cudaFuncSetAttribute(k_bin,  cudaFuncAttributeMaxDynamicSharedMemorySize, 73728);
    cudaFuncSetAttribute(k_degb, cudaFuncAttributeMaxDynamicSharedMemorySize, 65536);
    cudaFuncSetAttribute(k_aggb, cudaFuncAttributeMaxDynamicSharedMemorySize, 131072);
    (void)attr_done;

    const int T = 256;
    int nb_n = (n + T - 1) / T;
    int nb_bin = (e + BIN_TILE - 1) / BIN_TILE;
    int nb_agg = NCB * GRP;

    k_init<<<nb_n, T>>>(n);
    k_bin<<<nb_bin, BIN_THR, 73728>>>(row, col, e);
    k_degb<<<nb_agg, AGG_THR, 65536>>>(n);
    k_phase1<<<nb_n, T>>>(x, n);
    k_aggb<<<nb_agg, AGG_THR, 131072>>>(n);
    k_phase2<<<nb_n, T>>>(W1, b1, W2, n);
    k_aggb<<<nb_agg, AGG_THR, 131072>>>(n);
    k_out<<<nb_n, T>>>(out, b2, n);
}